// round 15
// baseline (speedup 1.0000x reference)
#include <cuda_runtime.h>
#include <cuda_fp16.h>
#include <cstdint>

// support: (2,5,1024,128) -> d_in[0]
// query:   (2,4,1024,128) -> d_in[1]
// out:     (2,4,5,1024,1024) fp32
// sim[b,i,j,m,n] = <q_norm[b,i,m,:], s_norm[b,j,n,:]>
//
// Single-pass fp16 HMMA (rel_err ~2.9e-4 measured).
// CTA 128x128, 4 warps (2x2), warp tile 64x64. 2 macro-steps of K64,
// double-buffered cp.async. R14: epilogue transposes accumulators
// through the (dead) stage buffers so global stores are STG.128 covering
// full 256B row segments (4 lines/instr instead of 8 lines per STG.64).

#define NQ_ROWS 8192
#define NS_ROWS 10240
#define KDIM 128

__device__ __align__(16) __half g_qs[NQ_ROWS * KDIM];
__device__ __align__(16) __half g_ss[NS_ROWS * KDIM];

__device__ __forceinline__ uint32_t smem_u32(const void* p) {
    uint32_t a;
    asm("{ .reg .u64 t; cvta.to.shared.u64 t, %1; cvt.u32.u64 %0, t; }"
        : "=r"(a) : "l"(p));
    return a;
}

__device__ __forceinline__ void ldm_x4(uint32_t* r, uint32_t addr) {
    asm volatile("ldmatrix.sync.aligned.m8n8.x4.shared.b16 {%0,%1,%2,%3}, [%4];"
        : "=r"(r[0]), "=r"(r[1]), "=r"(r[2]), "=r"(r[3]) : "r"(addr));
}

__device__ __forceinline__ void mma16816(float* d, const uint32_t* a,
                                         const uint32_t* b) {
    asm volatile(
        "mma.sync.aligned.m16n8k16.row.col.f32.f16.f16.f32 "
        "{%0,%1,%2,%3}, {%4,%5,%6,%7}, {%8,%9}, {%0,%1,%2,%3};"
        : "+f"(d[0]), "+f"(d[1]), "+f"(d[2]), "+f"(d[3])
        : "r"(a[0]), "r"(a[1]), "r"(a[2]), "r"(a[3]), "r"(b[0]), "r"(b[1]));
}

#define CP_ASYNC16(dst, src) \
    asm volatile("cp.async.cg.shared.global [%0], [%1], 16;" \
        :: "r"(dst), "l"(src) : "memory")
#define CP_COMMIT() asm volatile("cp.async.commit_group;" ::: "memory")
#define CP_WAIT(n)  asm volatile("cp.async.wait_group %0;" :: "n"(n) : "memory")

// ---------------------------------------------------------------------------
// Kernel 1: normalize rows -> fp16. One warp per row.
// ---------------------------------------------------------------------------
__global__ void normalize_kernel(const float* __restrict__ s,
                                 const float* __restrict__ q) {
    int warp_id = (blockIdx.x * blockDim.x + threadIdx.x) >> 5;
    int lane    = threadIdx.x & 31;
    if (warp_id >= NQ_ROWS + NS_ROWS) return;

    bool is_q = warp_id < NQ_ROWS;
    const float* src = is_q ? q + (size_t)warp_id * KDIM
                            : s + (size_t)(warp_id - NQ_ROWS) * KDIM;
    __half* dst = is_q ? g_qs + (size_t)warp_id * KDIM
                       : g_ss + (size_t)(warp_id - NQ_ROWS) * KDIM;

    float4 v = reinterpret_cast<const float4*>(src)[lane];
    float ssum = v.x * v.x + v.y * v.y + v.z * v.z + v.w * v.w;
    #pragma unroll
    for (int o = 16; o > 0; o >>= 1)
        ssum += __shfl_xor_sync(0xffffffffu, ssum, o);
    float rn = 1.0f / fmaxf(sqrtf(ssum), 1e-12f);

    __half h[4] = {__float2half_rn(v.x * rn), __float2half_rn(v.y * rn),
                   __float2half_rn(v.z * rn), __float2half_rn(v.w * rn)};
    *reinterpret_cast<uint2*>(dst + lane * 4) = *reinterpret_cast<uint2*>(h);
}

// ---------------------------------------------------------------------------
// Kernel 2: pipelined HMMA GEMM. CTA 128x128, 4 warps 2(m)x2(n),
// warp tile 64x64. 2 macro-steps of K64 double-buffered in smem.
// Rows 64 fp16 = 128B, 16B-chunk XOR swizzle (ch ^ (row&7)).
// Epilogue: smem transpose (scratch = dead stage buffers, 32 rows x 68
// floats per warp-half) -> STG.128 full-row-segment coalesced stores.
// ---------------------------------------------------------------------------
#define CHUNK_A 16384
#define CHUNK_B 16384
#define BUF_BYTES (CHUNK_A + CHUNK_B)   // 32KB per stage
#define SMEM_BYTES (2 * BUF_BYTES)      // 64KB
#define SCR_STRIDE 68                    // floats per scratch row (pad 4)

__global__ __launch_bounds__(128, 2)
void cosine_hmma_kernel(float* __restrict__ out) {
    extern __shared__ __align__(1024) char smem[];

    int tid  = threadIdx.x;
    int wid  = tid >> 5;
    int lane = tid & 31;

    int p  = blockIdx.z;          // (b*4+i)*5 + j
    int b  = p / 20;
    int ij = p % 20;
    int i  = ij / 5;
    int j  = ij % 5;
    int m0 = blockIdx.y * 128;
    int n0 = blockIdx.x * 128;

    const __half* abase = g_qs + (size_t)((b * 4 + i) * 1024 + m0) * KDIM;
    const __half* bbase = g_ss + (size_t)((b * 5 + j) * 1024 + n0) * KDIM;

    uint32_t smem0 = smem_u32(smem);

    auto load_step = [&](int s) {
        uint32_t bufA = smem0 + (uint32_t)(s & 1) * BUF_BYTES;
        uint32_t bufB = bufA + CHUNK_A;
        int col = s * 64;
        #pragma unroll
        for (int it = 0; it < 8; it++) {
            int lin = tid + it * 128;    // 0..1023
            int row = lin >> 3;          // 0..127
            int ch  = lin & 7;           // 16B chunks of 128B row
            uint32_t doff = (uint32_t)row * 128u + (uint32_t)((ch ^ (row & 7)) << 4);
            CP_ASYNC16(bufA + doff, abase + (size_t)row * KDIM + col + ch * 8);
            CP_ASYNC16(bufB + doff, bbase + (size_t)row * KDIM + col + ch * 8);
        }
        CP_COMMIT();
    };

    // ---- warp tiling: 2 warps over m (64 each), 2 over n (64 each) ----
    int wm = wid >> 1;
    int wn = wid & 1;
    int mbase = wm * 64;
    int nbase = wn * 64;

    int a_mi   = lane >> 3;
    int a_row0 = mbase + (a_mi & 1) * 8 + (lane & 7);         // + mt*16
    int a_koff = (a_mi >> 1) * 8;
    int b_row0 = nbase + ((lane >> 4) & 1) * 8 + (lane & 7);  // + nt2*16
    int b_koff = ((lane >> 3) & 1) * 8;

    float acc[4][8][4];
    #pragma unroll
    for (int mt = 0; mt < 4; mt++)
        #pragma unroll
        for (int nt = 0; nt < 8; nt++)
            #pragma unroll
            for (int e = 0; e < 4; e++)
                acc[mt][nt][e] = 0.0f;

    auto mma_stage = [&](int s) {
        uint32_t bufA = smem0 + (uint32_t)(s & 1) * BUF_BYTES;
        uint32_t bufB = bufA + CHUNK_A;
        #pragma unroll
        for (int ks = 0; ks < 4; ks++) {
            int ka = ks * 16 + a_koff;
            int kb = ks * 16 + b_koff;

            uint32_t aF[4][4];
            #pragma unroll
            for (int mt = 0; mt < 4; mt++) {
                int row = a_row0 + mt * 16;
                uint32_t addr = bufA + (uint32_t)row * 128u
                              + (uint32_t)((((ka >> 3) ^ (row & 7)) << 4));
                ldm_x4(aF[mt], addr);
            }
            uint32_t bF[4][4];
            #pragma unroll
            for (int nt2 = 0; nt2 < 4; nt2++) {
                int row = b_row0 + nt2 * 16;
                uint32_t addr = bufB + (uint32_t)row * 128u
                              + (uint32_t)((((kb >> 3) ^ (row & 7)) << 4));
                ldm_x4(bF[nt2], addr);
            }

            #pragma unroll
            for (int mt = 0; mt < 4; mt++)
                #pragma unroll
                for (int nt = 0; nt < 8; nt++)
                    mma16816(acc[mt][nt], aF[mt], &bF[nt >> 1][(nt & 1) * 2]);
        }
    };

    // ---- 2-stage pipeline, one sync per stage ----
    load_step(0);
    load_step(1);

    CP_WAIT(1);
    __syncthreads();
    mma_stage(0);

    CP_WAIT(0);
    __syncthreads();
    mma_stage(1);

    // All warps done with stage buffers before reuse as epilogue scratch.
    __syncthreads();

    // ---- Epilogue: transpose via per-warp scratch, coalesced STG.128 ----
    // Scratch: 32 rows x 68 floats per warp = 8704 floats (34816B total).
    {
        float* scr = reinterpret_cast<float*>(smem) + wid * (32 * SCR_STRIDE);
        int tr  = lane >> 2;
        int tc2 = (lane & 3) * 2;
        size_t obase = ((size_t)p << 20)
                     + (size_t)(m0 + mbase) * 1024 + (n0 + nbase);

        int rrow = lane >> 4;        // 0..1  (read phase: 2 rows per iter)
        int seg  = lane & 15;        // 0..15 (16B segment within 256B row)

        #pragma unroll
        for (int h = 0; h < 2; h++) {
            // STS phase: mt pair {2h, 2h+1} -> local rows 0..31
            #pragma unroll
            for (int mh = 0; mh < 2; mh++) {
                int mt = h * 2 + mh;
                int r0 = mh * 16 + tr;        // 0..15 within pair
                #pragma unroll
                for (int nt = 0; nt < 8; nt++) {
                    float* d0 = scr + (size_t)r0 * SCR_STRIDE + nt * 8 + tc2;
                    d0[0] = acc[mt][nt][0];
                    d0[1] = acc[mt][nt][1];
                    float* d1 = d0 + 8 * SCR_STRIDE;
                    d1[0] = acc[mt][nt][2];
                    d1[1] = acc[mt][nt][3];
                }
            }
            __syncwarp();

            // LDS.128 + STG.128 phase: 32 rows x 256B, 2 rows per iter
            #pragma unroll
            for (int it = 0; it < 16; it++) {
                int r = it * 2 + rrow;        // 0..31 local
                float4 v = *reinterpret_cast<float4*>(
                    scr + (size_t)r * SCR_STRIDE + seg * 4);
                int gr = h * 32 + r;          // row within warp tile
                *reinterpret_cast<float4*>(
                    out + obase + (size_t)gr * 1024 + seg * 4) = v;
            }
            __syncwarp();
        }
    }
}

extern "C" void kernel_launch(void* const* d_in, const int* in_sizes, int n_in,
                              void* d_out, int out_size) {
    const float* support = (const float*)d_in[0];
    const float* query   = (const float*)d_in[1];
    float* out = (float*)d_out;

    cudaFuncSetAttribute(cosine_hmma_kernel,
                         cudaFuncAttributeMaxDynamicSharedMemorySize, SMEM_BYTES);

    int total_rows = NQ_ROWS + NS_ROWS;
    int blocks1 = (total_rows + 7) / 8;
    normalize_kernel<<<blocks1, 256>>>(support, query);

    dim3 grid(8, 8, 40);
    cosine_hmma_kernel<<<grid, 128, SMEM_BYTES>>>(out);
}

// round 16
// speedup vs baseline: 1.6183x; 1.6183x over previous
#include <cuda_runtime.h>
#include <cuda_fp16.h>
#include <cstdint>

// support: (2,5,1024,128) -> d_in[0]
// query:   (2,4,1024,128) -> d_in[1]
// out:     (2,4,5,1024,1024) fp32
// sim[b,i,j,m,n] = <q_norm[b,i,m,:], s_norm[b,j,n,:]>
//
// Single-pass fp16 HMMA (rel_err ~2.9e-4 measured).
// R16: PERSISTENT kernel — 296 CTAs (2/SM), each walks ~8-9 output tiles
// with a 3-buffer cp.async pipeline that stays primed ACROSS tiles
// (loads 2 stages ahead; empty commit groups keep wait_group uniform).
// CTA tile 128x128, 4 warps (2x2), warp tile 64x64, direct STG epilogue.

#define NQ_ROWS 8192
#define NS_ROWS 10240
#define KDIM 128
#define NTILES 2560
#define GRIDP 296

__device__ __align__(16) __half g_qs[NQ_ROWS * KDIM];
__device__ __align__(16) __half g_ss[NS_ROWS * KDIM];

__device__ __forceinline__ uint32_t smem_u32(const void* p) {
    uint32_t a;
    asm("{ .reg .u64 t; cvta.to.shared.u64 t, %1; cvt.u32.u64 %0, t; }"
        : "=r"(a) : "l"(p));
    return a;
}

__device__ __forceinline__ void ldm_x4(uint32_t* r, uint32_t addr) {
    asm volatile("ldmatrix.sync.aligned.m8n8.x4.shared.b16 {%0,%1,%2,%3}, [%4];"
        : "=r"(r[0]), "=r"(r[1]), "=r"(r[2]), "=r"(r[3]) : "r"(addr));
}

__device__ __forceinline__ void mma16816(float* d, const uint32_t* a,
                                         const uint32_t* b) {
    asm volatile(
        "mma.sync.aligned.m16n8k16.row.col.f32.f16.f16.f32 "
        "{%0,%1,%2,%3}, {%4,%5,%6,%7}, {%8,%9}, {%0,%1,%2,%3};"
        : "+f"(d[0]), "+f"(d[1]), "+f"(d[2]), "+f"(d[3])
        : "r"(a[0]), "r"(a[1]), "r"(a[2]), "r"(a[3]), "r"(b[0]), "r"(b[1]));
}

#define CP_ASYNC16(dst, src) \
    asm volatile("cp.async.cg.shared.global [%0], [%1], 16;" \
        :: "r"(dst), "l"(src) : "memory")
#define CP_COMMIT() asm volatile("cp.async.commit_group;" ::: "memory")
#define CP_WAIT(n)  asm volatile("cp.async.wait_group %0;" :: "n"(n) : "memory")

// ---------------------------------------------------------------------------
// Kernel 1: normalize rows -> fp16. One warp per row.
// ---------------------------------------------------------------------------
__global__ void normalize_kernel(const float* __restrict__ s,
                                 const float* __restrict__ q) {
    int warp_id = (blockIdx.x * blockDim.x + threadIdx.x) >> 5;
    int lane    = threadIdx.x & 31;
    if (warp_id >= NQ_ROWS + NS_ROWS) return;

    bool is_q = warp_id < NQ_ROWS;
    const float* src = is_q ? q + (size_t)warp_id * KDIM
                            : s + (size_t)(warp_id - NQ_ROWS) * KDIM;
    __half* dst = is_q ? g_qs + (size_t)warp_id * KDIM
                       : g_ss + (size_t)(warp_id - NQ_ROWS) * KDIM;

    float4 v = reinterpret_cast<const float4*>(src)[lane];
    float ssum = v.x * v.x + v.y * v.y + v.z * v.z + v.w * v.w;
    #pragma unroll
    for (int o = 16; o > 0; o >>= 1)
        ssum += __shfl_xor_sync(0xffffffffu, ssum, o);
    float rn = 1.0f / fmaxf(sqrtf(ssum), 1e-12f);

    __half h[4] = {__float2half_rn(v.x * rn), __float2half_rn(v.y * rn),
                   __float2half_rn(v.z * rn), __float2half_rn(v.w * rn)};
    *reinterpret_cast<uint2*>(dst + lane * 4) = *reinterpret_cast<uint2*>(h);
}

// ---------------------------------------------------------------------------
// Tile index -> A/B global bases.  t = ((p*8)+my)*8 + nx
// ---------------------------------------------------------------------------
__device__ __forceinline__ void tile_bases(int t, const __half** pa,
                                           const __half** pb) {
    int p  = t >> 6;
    int r  = t & 63;
    int my = r >> 3;
    int nx = r & 7;
    int b  = p / 20;
    int ij = p % 20;
    int i  = ij / 5;
    int j  = ij % 5;
    *pa = g_qs + (size_t)((b * 4 + i) * 1024 + my * 128) * KDIM;
    *pb = g_ss + (size_t)((b * 5 + j) * 1024 + nx * 128) * KDIM;
}

// ---------------------------------------------------------------------------
// Kernel 2: persistent pipelined HMMA GEMM.
// Stage = K64 chunk of one tile (2 stages/tile). 3 buffers of 32KB.
// Rows 64 fp16 = 128B, 16B-chunk XOR swizzle (ch ^ (row&7)).
// ---------------------------------------------------------------------------
#define CHUNK_A 16384
#define CHUNK_B 16384
#define BUF_BYTES (CHUNK_A + CHUNK_B)   // 32KB per stage
#define NBUF 3
#define SMEM_BYTES (NBUF * BUF_BYTES)   // 96KB

__global__ __launch_bounds__(128, 2)
void cosine_hmma_kernel(float* __restrict__ out) {
    extern __shared__ __align__(1024) char smem[];

    int tid  = threadIdx.x;
    int wid  = tid >> 5;
    int lane = tid & 31;

    uint32_t smem0 = smem_u32(smem);

    // ---- load cursor (advances one stage per issue_load call) ----
    int lt = blockIdx.x;
    int ls = 0;
    const __half *la = nullptr, *lb = nullptr;
    if (lt < NTILES) tile_bases(lt, &la, &lb);

    auto issue_load = [&](int g) {
        if (lt < NTILES) {
            uint32_t bufA = smem0 + (uint32_t)(g % NBUF) * BUF_BYTES;
            uint32_t bufB = bufA + CHUNK_A;
            int col = ls * 64;
            #pragma unroll
            for (int it = 0; it < 8; it++) {
                int lin = tid + it * 128;    // 0..1023
                int row = lin >> 3;          // 0..127
                int ch  = lin & 7;
                uint32_t doff = (uint32_t)row * 128u
                              + (uint32_t)((ch ^ (row & 7)) << 4);
                CP_ASYNC16(bufA + doff, la + (size_t)row * KDIM + col + ch * 8);
                CP_ASYNC16(bufB + doff, lb + (size_t)row * KDIM + col + ch * 8);
            }
        }
        CP_COMMIT();   // empty group past the end keeps accounting uniform
        if (++ls == 2) {
            ls = 0;
            lt += GRIDP;
            if (lt < NTILES) tile_bases(lt, &la, &lb);
        }
    };

    // ---- warp tiling: 2 warps over m (64 each), 2 over n (64 each) ----
    int wm = wid >> 1;
    int wn = wid & 1;
    int mbase = wm * 64;
    int nbase = wn * 64;

    int a_mi   = lane >> 3;
    int a_row0 = mbase + (a_mi & 1) * 8 + (lane & 7);         // + mt*16
    int a_koff = (a_mi >> 1) * 8;
    int b_row0 = nbase + ((lane >> 4) & 1) * 8 + (lane & 7);  // + nt2*16
    int b_koff = ((lane >> 3) & 1) * 8;

    float acc[4][8][4];

    auto mma_stage = [&](int g) {
        uint32_t bufA = smem0 + (uint32_t)(g % NBUF) * BUF_BYTES;
        uint32_t bufB = bufA + CHUNK_A;
        #pragma unroll
        for (int ks = 0; ks < 4; ks++) {
            int ka = ks * 16 + a_koff;
            int kb = ks * 16 + b_koff;

            uint32_t aF[4][4];
            #pragma unroll
            for (int mt = 0; mt < 4; mt++) {
                int row = a_row0 + mt * 16;
                uint32_t addr = bufA + (uint32_t)row * 128u
                              + (uint32_t)((((ka >> 3) ^ (row & 7)) << 4));
                ldm_x4(aF[mt], addr);
            }
            uint32_t bF[4][4];
            #pragma unroll
            for (int nt2 = 0; nt2 < 4; nt2++) {
                int row = b_row0 + nt2 * 16;
                uint32_t addr = bufB + (uint32_t)row * 128u
                              + (uint32_t)((((kb >> 3) ^ (row & 7)) << 4));
                ldm_x4(bF[nt2], addr);
            }

            #pragma unroll
            for (int mt = 0; mt < 4; mt++)
                #pragma unroll
                for (int nt = 0; nt < 8; nt++)
                    mma16816(acc[mt][nt], aF[mt], &bF[nt >> 1][(nt & 1) * 2]);
        }
    };

    // ---- prime the pipeline 2 stages deep ----
    issue_load(0);
    issue_load(1);

    int g = 0;
    int tr  = lane >> 2;
    int tc2 = (lane & 3) * 2;

    for (int ct = blockIdx.x; ct < NTILES; ct += GRIDP) {
        #pragma unroll
        for (int mt = 0; mt < 4; mt++)
            #pragma unroll
            for (int nt = 0; nt < 8; nt++)
                #pragma unroll
                for (int e = 0; e < 4; e++)
                    acc[mt][nt][e] = 0.0f;

        #pragma unroll
        for (int s = 0; s < 2; s++, g++) {
            CP_WAIT(1);          // stage g resident (g+1 may pend)
            __syncthreads();     // all warps done with buf (g-1)%3, data vis.
            issue_load(g + 2);   // into buf (g+2)%3 (= (g-1)%3, now free)
            mma_stage(g);
        }

        // ---- Epilogue: direct fragment stores (tile ct) ----
        int p  = ct >> 6;
        int r  = ct & 63;
        int my = r >> 3;
        int nx = r & 7;
        size_t obase = ((size_t)p << 20)
                     + (size_t)(my * 128 + mbase) * 1024 + (nx * 128 + nbase);
        #pragma unroll
        for (int mt = 0; mt < 4; mt++) {
            #pragma unroll
            for (int nt = 0; nt < 8; nt++) {
                float* r0 = out + obase + (size_t)(mt * 16 + tr) * 1024
                          + nt * 8 + tc2;
                *reinterpret_cast<float2*>(r0) =
                    make_float2(acc[mt][nt][0], acc[mt][nt][1]);
                *reinterpret_cast<float2*>(r0 + 8 * 1024) =
                    make_float2(acc[mt][nt][2], acc[mt][nt][3]);
            }
        }
    }
}

extern "C" void kernel_launch(void* const* d_in, const int* in_sizes, int n_in,
                              void* d_out, int out_size) {
    const float* support = (const float*)d_in[0];
    const float* query   = (const float*)d_in[1];
    float* out = (float*)d_out;

    cudaFuncSetAttribute(cosine_hmma_kernel,
                         cudaFuncAttributeMaxDynamicSharedMemorySize, SMEM_BYTES);

    int total_rows = NQ_ROWS + NS_ROWS;
    int blocks1 = (total_rows + 7) / 8;
    normalize_kernel<<<blocks1, 256>>>(support, query);

    cosine_hmma_kernel<<<GRIDP, 128, SMEM_BYTES>>>(out);
}

// round 17
// speedup vs baseline: 1.6819x; 1.0393x over previous
#include <cuda_runtime.h>
#include <cuda_fp16.h>
#include <cstdint>

// support: (2,5,1024,128) -> d_in[0]
// query:   (2,4,1024,128) -> d_in[1]
// out:     (2,4,5,1024,1024) fp32
// sim[b,i,j,m,n] = <q_norm[b,i,m,:], s_norm[b,j,n,:]>
//
// Single-pass fp16 HMMA (rel_err ~2.9e-4 measured).
// GEMM = R12 champion config verbatim: CTA 128x128, 4 warps (2x2),
// warp tile 64x64, 2 macro-steps of K64, double-buffered cp.async,
// 64KB smem/CTA -> 2 CTAs/SM, direct STG epilogue.
// R17 change: normalize kernel handles 2 rows/warp (16-lane halves,
// uint4 stores) to trim the non-GEMM overhead.

#define NQ_ROWS 8192
#define NS_ROWS 10240
#define KDIM 128

__device__ __align__(16) __half g_qs[NQ_ROWS * KDIM];
__device__ __align__(16) __half g_ss[NS_ROWS * KDIM];

__device__ __forceinline__ uint32_t smem_u32(const void* p) {
    uint32_t a;
    asm("{ .reg .u64 t; cvta.to.shared.u64 t, %1; cvt.u32.u64 %0, t; }"
        : "=r"(a) : "l"(p));
    return a;
}

__device__ __forceinline__ void ldm_x4(uint32_t* r, uint32_t addr) {
    asm volatile("ldmatrix.sync.aligned.m8n8.x4.shared.b16 {%0,%1,%2,%3}, [%4];"
        : "=r"(r[0]), "=r"(r[1]), "=r"(r[2]), "=r"(r[3]) : "r"(addr));
}

__device__ __forceinline__ void mma16816(float* d, const uint32_t* a,
                                         const uint32_t* b) {
    asm volatile(
        "mma.sync.aligned.m16n8k16.row.col.f32.f16.f16.f32 "
        "{%0,%1,%2,%3}, {%4,%5,%6,%7}, {%8,%9}, {%0,%1,%2,%3};"
        : "+f"(d[0]), "+f"(d[1]), "+f"(d[2]), "+f"(d[3])
        : "r"(a[0]), "r"(a[1]), "r"(a[2]), "r"(a[3]), "r"(b[0]), "r"(b[1]));
}

#define CP_ASYNC16(dst, src) \
    asm volatile("cp.async.cg.shared.global [%0], [%1], 16;" \
        :: "r"(dst), "l"(src) : "memory")
#define CP_COMMIT() asm volatile("cp.async.commit_group;" ::: "memory")
#define CP_WAIT(n)  asm volatile("cp.async.wait_group %0;" :: "n"(n) : "memory")

// ---------------------------------------------------------------------------
// Kernel 1: normalize rows -> fp16. TWO rows per warp (16-lane halves);
// each lane covers 8 elements and stores 16B (256B coalesced per half).
// ---------------------------------------------------------------------------
__global__ void normalize_kernel(const float* __restrict__ s,
                                 const float* __restrict__ q) {
    int gwarp = (blockIdx.x * blockDim.x + threadIdx.x) >> 5;
    int lane  = threadIdx.x & 31;
    int half  = lane >> 4;          // 0 or 1
    int hl    = lane & 15;          // 0..15

    int row = gwarp * 2 + half;
    if (row >= NQ_ROWS + NS_ROWS) return;

    bool is_q = row < NQ_ROWS;
    const float* src = is_q ? q + (size_t)row * KDIM
                            : s + (size_t)(row - NQ_ROWS) * KDIM;
    __half* dst = is_q ? g_qs + (size_t)row * KDIM
                       : g_ss + (size_t)(row - NQ_ROWS) * KDIM;

    float4 v0 = reinterpret_cast<const float4*>(src)[hl * 2];
    float4 v1 = reinterpret_cast<const float4*>(src)[hl * 2 + 1];
    float ssum = v0.x * v0.x + v0.y * v0.y + v0.z * v0.z + v0.w * v0.w
               + v1.x * v1.x + v1.y * v1.y + v1.z * v1.z + v1.w * v1.w;
    #pragma unroll
    for (int o = 8; o > 0; o >>= 1)
        ssum += __shfl_xor_sync(0xffffffffu, ssum, o);
    float rn = 1.0f / fmaxf(sqrtf(ssum), 1e-12f);

    __half h[8] = {__float2half_rn(v0.x * rn), __float2half_rn(v0.y * rn),
                   __float2half_rn(v0.z * rn), __float2half_rn(v0.w * rn),
                   __float2half_rn(v1.x * rn), __float2half_rn(v1.y * rn),
                   __float2half_rn(v1.z * rn), __float2half_rn(v1.w * rn)};
    *reinterpret_cast<uint4*>(dst + hl * 8) = *reinterpret_cast<uint4*>(h);
}

// ---------------------------------------------------------------------------
// Kernel 2: pipelined HMMA GEMM (R12 champion, verbatim).
// CTA 128x128, 4 warps 2(m)x2(n), warp tile 64x64.
// 2 macro-steps of K64, double-buffered. Rows 64 fp16 = 128B,
// 16B-chunk XOR swizzle (ch ^ (row&7)).
// ---------------------------------------------------------------------------
#define CHUNK_A 16384
#define CHUNK_B 16384
#define BUF_BYTES (CHUNK_A + CHUNK_B)   // 32KB per stage
#define SMEM_BYTES (2 * BUF_BYTES)      // 64KB

__global__ __launch_bounds__(128, 2)
void cosine_hmma_kernel(float* __restrict__ out) {
    extern __shared__ __align__(1024) char smem[];

    int tid  = threadIdx.x;
    int wid  = tid >> 5;
    int lane = tid & 31;

    int p  = blockIdx.z;          // (b*4+i)*5 + j
    int b  = p / 20;
    int ij = p % 20;
    int i  = ij / 5;
    int j  = ij % 5;
    int m0 = blockIdx.y * 128;
    int n0 = blockIdx.x * 128;

    const __half* abase = g_qs + (size_t)((b * 4 + i) * 1024 + m0) * KDIM;
    const __half* bbase = g_ss + (size_t)((b * 5 + j) * 1024 + n0) * KDIM;

    uint32_t smem0 = smem_u32(smem);

    auto load_step = [&](int s) {
        uint32_t bufA = smem0 + (uint32_t)(s & 1) * BUF_BYTES;
        uint32_t bufB = bufA + CHUNK_A;
        int col = s * 64;
        #pragma unroll
        for (int it = 0; it < 8; it++) {
            int lin = tid + it * 128;    // 0..1023
            int row = lin >> 3;          // 0..127
            int ch  = lin & 7;           // 16B chunks of 128B row
            uint32_t doff = (uint32_t)row * 128u + (uint32_t)((ch ^ (row & 7)) << 4);
            CP_ASYNC16(bufA + doff, abase + (size_t)row * KDIM + col + ch * 8);
            CP_ASYNC16(bufB + doff, bbase + (size_t)row * KDIM + col + ch * 8);
        }
        CP_COMMIT();
    };

    // ---- warp tiling: 2 warps over m (64 each), 2 over n (64 each) ----
    int wm = wid >> 1;
    int wn = wid & 1;
    int mbase = wm * 64;
    int nbase = wn * 64;

    int a_mi   = lane >> 3;
    int a_row0 = mbase + (a_mi & 1) * 8 + (lane & 7);         // + mt*16
    int a_koff = (a_mi >> 1) * 8;
    int b_row0 = nbase + ((lane >> 4) & 1) * 8 + (lane & 7);  // + nt2*16
    int b_koff = ((lane >> 3) & 1) * 8;

    float acc[4][8][4];
    #pragma unroll
    for (int mt = 0; mt < 4; mt++)
        #pragma unroll
        for (int nt = 0; nt < 8; nt++)
            #pragma unroll
            for (int e = 0; e < 4; e++)
                acc[mt][nt][e] = 0.0f;

    auto mma_stage = [&](int s) {
        uint32_t bufA = smem0 + (uint32_t)(s & 1) * BUF_BYTES;
        uint32_t bufB = bufA + CHUNK_A;
        #pragma unroll
        for (int ks = 0; ks < 4; ks++) {
            int ka = ks * 16 + a_koff;
            int kb = ks * 16 + b_koff;

            uint32_t aF[4][4];
            #pragma unroll
            for (int mt = 0; mt < 4; mt++) {
                int row = a_row0 + mt * 16;
                uint32_t addr = bufA + (uint32_t)row * 128u
                              + (uint32_t)((((ka >> 3) ^ (row & 7)) << 4));
                ldm_x4(aF[mt], addr);
            }
            uint32_t bF[4][4];
            #pragma unroll
            for (int nt2 = 0; nt2 < 4; nt2++) {
                int row = b_row0 + nt2 * 16;
                uint32_t addr = bufB + (uint32_t)row * 128u
                              + (uint32_t)((((kb >> 3) ^ (row & 7)) << 4));
                ldm_x4(bF[nt2], addr);
            }

            #pragma unroll
            for (int mt = 0; mt < 4; mt++)
                #pragma unroll
                for (int nt = 0; nt < 8; nt++)
                    mma16816(acc[mt][nt], aF[mt], &bF[nt >> 1][(nt & 1) * 2]);
        }
    };

    // ---- 2-stage pipeline, one sync per stage ----
    load_step(0);
    load_step(1);

    CP_WAIT(1);
    __syncthreads();
    mma_stage(0);

    CP_WAIT(0);
    __syncthreads();
    mma_stage(1);

    // ---- Epilogue: direct fragment stores (32B contiguous per quad) ----
    int tr  = lane >> 2;
    int tc2 = (lane & 3) * 2;
    size_t obase = ((size_t)p << 20)
                 + (size_t)(m0 + mbase) * 1024 + (n0 + nbase);
    #pragma unroll
    for (int mt = 0; mt < 4; mt++) {
        #pragma unroll
        for (int nt = 0; nt < 8; nt++) {
            float* r0 = out + obase + (size_t)(mt * 16 + tr) * 1024 + nt * 8 + tc2;
            *reinterpret_cast<float2*>(r0) =
                make_float2(acc[mt][nt][0], acc[mt][nt][1]);
            *reinterpret_cast<float2*>(r0 + 8 * 1024) =
                make_float2(acc[mt][nt][2], acc[mt][nt][3]);
        }
    }
}

extern "C" void kernel_launch(void* const* d_in, const int* in_sizes, int n_in,
                              void* d_out, int out_size) {
    const float* support = (const float*)d_in[0];
    const float* query   = (const float*)d_in[1];
    float* out = (float*)d_out;

    cudaFuncSetAttribute(cosine_hmma_kernel,
                         cudaFuncAttributeMaxDynamicSharedMemorySize, SMEM_BYTES);

    // 18432 rows, 2 rows per warp -> 9216 warps -> 1152 blocks of 256 thr.
    int total_warps = (NQ_ROWS + NS_ROWS + 1) / 2;
    int blocks1 = (total_warps + 7) / 8;
    normalize_kernel<<<blocks1, 256>>>(support, query);

    dim3 grid(8, 8, 40);
    cosine_hmma_kernel<<<grid, 128, SMEM_BYTES>>>(out);
}